// round 6
// baseline (speedup 1.0000x reference)
#include <cuda_runtime.h>
#include <cuda_fp16.h>
#include <cstdint>
#include <math.h>

// ---------------- problem constants ----------------
#define T_TOK 4096
#define DD    1024
#define HH    2048
#define EE    8
#define CAP   4096
#define NEXP  9          // 8 routed + shared as "expert 8"

// ---------------- tile config ----------------
#define BM 128
#define BN 128
#define BK 64            // k halfs per chunk (128B rows -> SW128)
#define NSTAGE 3
#define S_B   16384      // B plane offset inside a stage
#define STG   32768      // stage bytes: A 16KB + B 16KB
#define SMEM_DYN (NSTAGE * STG)   // 98304

typedef unsigned int u32;
typedef unsigned long long u64;

// ---------------- device scratch ----------------
__device__ int   g_cnt[EE];
__device__ int   g_tok[EE * CAP];
__device__ float g_wt [EE * CAP];
__device__ __half g_xh [(size_t)T_TOK * DD];
__device__ __half g_wgu[(size_t)NEXP * 4096 * DD];   // interleaved gate/up rows
__device__ __half g_wd [(size_t)NEXP * DD * HH];
__device__ __half g_hh [(size_t)NEXP * CAP * HH];

// ---------------- helpers ----------------
__device__ __forceinline__ u32 smem_u32(const void* p) {
    u32 a; asm("{ .reg .u64 t; cvta.to.shared.u64 t, %1; cvt.u32.u64 %0, t; }" : "=r"(a) : "l"(p));
    return a;
}
__device__ __forceinline__ void cpa16(u32 dst, const void* gsrc) {
    asm volatile("cp.async.cg.shared.global [%0], [%1], 16;" :: "r"(dst), "l"(gsrc) : "memory");
}
#define CP_COMMIT() asm volatile("cp.async.commit_group;" ::: "memory")
#define CP_WAIT(n)  asm volatile("cp.async.wait_group %0;" :: "n"(n) : "memory")

__device__ __forceinline__ void ldsm4(u32* r, u32 addr) {
    asm volatile("ldmatrix.sync.aligned.m8n8.x4.shared.b16 {%0,%1,%2,%3}, [%4];"
        : "=r"(r[0]), "=r"(r[1]), "=r"(r[2]), "=r"(r[3]) : "r"(addr));
}
__device__ __forceinline__ void mma16816(float* c, const u32* a, u32 b0, u32 b1) {
    asm volatile("mma.sync.aligned.m16n8k16.row.col.f32.f16.f16.f32 "
        "{%0,%1,%2,%3}, {%4,%5,%6,%7}, {%8,%9}, {%0,%1,%2,%3};"
        : "+f"(c[0]), "+f"(c[1]), "+f"(c[2]), "+f"(c[3])
        : "r"(a[0]), "r"(a[1]), "r"(a[2]), "r"(a[3]), "r"(b0), "r"(b1));
}
__device__ __forceinline__ uint2 pack_hi(float4 v) {
    __half2 h0 = __floats2half2_rn(v.x, v.y);
    __half2 h1 = __floats2half2_rn(v.z, v.w);
    uint2 r; r.x = *(u32*)&h0; r.y = *(u32*)&h1; return r;
}

// ---------------- kernel 0: zero output + counters ----------------
__global__ void zero_kernel(float4* out4, int n4) {
    int i = blockIdx.x * blockDim.x + threadIdx.x;
    if (i < n4) out4[i] = make_float4(0.f, 0.f, 0.f, 0.f);
    if (blockIdx.x == 0 && threadIdx.x < EE) g_cnt[threadIdx.x] = 0;
}

// ---------------- conversion kernels ----------------
__global__ void conv_x_kernel(const float* __restrict__ x) {
    int t = blockIdx.x, c = threadIdx.x;               // 256 thr = DD/4
    float4 v = ((const float4*)(x + (size_t)t * DD))[c];
    ((uint2*)g_xh)[(size_t)t * 256 + c] = pack_hi(v);
}
__global__ void conv_wgu_kernel(const float* __restrict__ Wg, const float* __restrict__ Wu,
                                const float* __restrict__ sg, const float* __restrict__ su) {
    int b = blockIdx.x;                                 // row in [0, NEXP*4096)
    int e = b >> 12, r = b & 4095;
    const float* src;
    if (e < EE) src = ((r & 1) ? Wu : Wg) + ((size_t)e * HH + (size_t)(r >> 1)) * DD;
    else        src = ((r & 1) ? su : sg) + (size_t)(r >> 1) * DD;
    float4 v = ((const float4*)src)[threadIdx.x];
    ((uint2*)g_wgu)[(size_t)b * 256 + threadIdx.x] = pack_hi(v);
}
__global__ void conv_wd_kernel(const float* __restrict__ Wd, const float* __restrict__ sd) {
    int b = blockIdx.x;                                 // row in [0, NEXP*DD), 512 thr
    int e = b >> 10, d = b & 1023;
    const float* src = (e < EE) ? Wd + ((size_t)e * DD + (size_t)d) * HH
                                : sd + (size_t)d * HH;
    float4 v = ((const float4*)src)[threadIdx.x];
    ((uint2*)g_wd)[(size_t)b * 512 + threadIdx.x] = pack_hi(v);
}

// ---------------- router ----------------
__global__ void router_kernel(const float* __restrict__ x,
                              const float* __restrict__ wr) {
    int t = blockIdx.x, w = threadIdx.x >> 5, lane = threadIdx.x & 31;
    const float* xr = x + (size_t)t * DD;
    const float* wrow = wr + (size_t)w * DD;
    float s = 0.f;
    for (int d = lane; d < DD; d += 32) s += xr[d] * wrow[d];
    #pragma unroll
    for (int o = 16; o; o >>= 1) s += __shfl_xor_sync(0xffffffffu, s, o);
    __shared__ float lg[EE];
    if (lane == 0) lg[w] = s;
    __syncthreads();
    if (threadIdx.x == 0) {
        int i0 = 0; float m0 = lg[0];
        #pragma unroll
        for (int j = 1; j < EE; ++j) if (lg[j] > m0) { m0 = lg[j]; i0 = j; }
        int i1 = -1; float m1 = -INFINITY;
        #pragma unroll
        for (int j = 0; j < EE; ++j) if (j != i0 && lg[j] > m1) { m1 = lg[j]; i1 = j; }
        float w0 = 1.f / (1.f + expf(m1 - m0));
        float w1 = 1.f - w0;
        int p0 = atomicAdd(&g_cnt[i0], 1);
        g_tok[i0 * CAP + p0] = t; g_wt[i0 * CAP + p0] = w0;
        int p1 = atomicAdd(&g_cnt[i1], 1);
        g_tok[i1 * CAP + p1] = t; g_wt[i1 * CAP + p1] = w1;
    }
}

// ---------------- shared GEMM machinery (128 threads, 4 warps, 64x64 warp tile) ----------------
// producer: thread t handles A row t and B row t, 8x 16B cp.async each per chunk.
// SW128 swizzle on 128B rows: dst = (row*128 + q*16) ^ ((row&7)<<4)
#define PROD_SETUP() \
    u32 pdA[8], pdB[8]; \
    { \
        u32 psw = (u32)((tid & 7) << 4); \
        _Pragma("unroll") \
        for (int q = 0; q < 8; ++q) { \
            u32 off = (((u32)(tid << 7) + (u32)(q << 4)) ^ psw); \
            pdA[q] = off; \
            pdB[q] = S_B + off; \
        } \
    }

#define ISSUE(s) do { \
    u32 _st = sb + (u32)((s) % NSTAGE) * STG; \
    const __half* _a = gsrcA + (size_t)(s) * BK; \
    const __half* _b = gsrcB + (size_t)(s) * BK; \
    _Pragma("unroll") \
    for (int q = 0; q < 8; ++q) { \
        cpa16(_st + pdA[q], _a + q * 8); \
        cpa16(_st + pdB[q], _b + q * 8); \
    } \
} while (0)

#define FRAG_SETUP() \
    int wm = wid & 1, wn = wid >> 1; \
    int lr = lane & 15, lkb = lane >> 4; \
    u32 fsw = (u32)((lr & 7) << 4); \
    u32 baseA[4], baseB[4]; \
    _Pragma("unroll") \
    for (int mb = 0; mb < 4; ++mb) \
        baseA[mb] = (u32)((wm * 64 + mb * 16 + lr) * 128 + lkb * 16); \
    _Pragma("unroll") \
    for (int nb = 0; nb < 4; ++nb) \
        baseB[nb] = (u32)(S_B + (wn * 64 + nb * 16 + lr) * 128 + lkb * 16); \
    float acc[4][8][4]; \
    _Pragma("unroll") \
    for (int a_ = 0; a_ < 4; ++a_) \
        _Pragma("unroll") \
        for (int b_ = 0; b_ < 8; ++b_) \
            _Pragma("unroll") \
            for (int c_ = 0; c_ < 4; ++c_) acc[a_][b_][c_] = 0.f;

#define CONSUME(cur) \
    _Pragma("unroll") \
    for (int ks = 0; ks < 4; ++ks) { \
        u32 af[4][4], bf[4][4]; \
        _Pragma("unroll") \
        for (int mb = 0; mb < 4; ++mb) \
            ldsm4(af[mb], (cur) + ((baseA[mb] + ks * 32) ^ fsw)); \
        _Pragma("unroll") \
        for (int nb = 0; nb < 4; ++nb) \
            ldsm4(bf[nb], (cur) + ((baseB[nb] + ks * 32) ^ fsw)); \
        _Pragma("unroll") \
        for (int mb = 0; mb < 4; ++mb) \
            _Pragma("unroll") \
            for (int nb = 0; nb < 4; ++nb) { \
                mma16816(acc[mb][nb * 2],     af[mb], bf[nb][0], bf[nb][2]); \
                mma16816(acc[mb][nb * 2 + 1], af[mb], bf[nb][1], bf[nb][3]); \
            } \
    }

#define MAINLOOP(NC) \
    ISSUE(0); CP_COMMIT(); \
    ISSUE(1); CP_COMMIT(); \
    for (int kt = 0; kt < (NC); ++kt) { \
        CP_WAIT(1); \
        __syncthreads(); \
        if (kt + 2 < (NC)) ISSUE(kt + 2); \
        CP_COMMIT(); \
        u32 cur = sb + (u32)(kt % NSTAGE) * STG; \
        CONSUME(cur); \
    }

// =====================================================================
// GEMM1: C[128,128] = Xg[128,1024] . Wgu^T ; epilogue SwiGLU -> g_hh
// =====================================================================
__global__ void __launch_bounds__(128, 2)
gemm1_kernel() {
    int e = blockIdx.z;
    int ne = (e == EE) ? T_TOK : g_cnt[e];
    int mbase = blockIdx.y * BM;
    if (mbase >= ne) return;
    int ntile = blockIdx.x;

    extern __shared__ char smem[];
    u32 sb = smem_u32(smem);
    __shared__ int s_tok[128];
    int tid = threadIdx.x, wid = tid >> 5, lane = tid & 31;
    {
        int r = mbase + tid;
        s_tok[tid] = (e == EE) ? r : ((r < ne) ? g_tok[e * CAP + r] : g_tok[e * CAP]);
    }
    __syncthreads();

    PROD_SETUP();
    const __half* gsrcA = g_xh + (size_t)s_tok[tid] * DD;
    const __half* gsrcB = g_wgu + (size_t)(e * 4096 + ntile * 128 + tid) * DD;

    FRAG_SETUP();
    MAINLOOP(DD / BK);   // 16 chunks

    // epilogue: SwiGLU -> fp16 h
    size_t slotBase = (size_t)e * CAP + mbase;
    int rq = lane >> 2, cq = lane & 3;
    #pragma unroll
    for (int mb = 0; mb < 4; ++mb)
        #pragma unroll
        for (int nt = 0; nt < 8; ++nt) {
            int nb = nt >> 1, h = nt & 1;
            int hcol = ntile * 64 + wn * 32 + nb * 8 + h * 4 + cq;
            float* c = acc[mb][nt];
            #pragma unroll
            for (int half = 0; half < 2; ++half) {
                int r = wm * 64 + mb * 16 + rq + half * 8;
                float gv = c[half * 2], uv = c[half * 2 + 1];
                float hv = (gv / (1.f + __expf(-gv))) * uv;
                g_hh[(slotBase + (size_t)r) * HH + (size_t)hcol] = __float2half_rn(hv);
            }
        }
}

// =====================================================================
// GEMM2: C[128,128] = h[128,2048] . Wd^T ; split-K=2; atomic scatter
// =====================================================================
__global__ void __launch_bounds__(128, 2)
gemm2_kernel(float* __restrict__ out) {
    int z = blockIdx.z;
    int e = z >> 1, kh = z & 1;
    int ne = (e == EE) ? T_TOK : g_cnt[e];
    int mbase = blockIdx.y * BM;
    if (mbase >= ne) return;
    int ntile = blockIdx.x;

    extern __shared__ char smem[];
    u32 sb = smem_u32(smem);
    __shared__ int   s_tok[128];
    __shared__ float s_wt[128];
    int tid = threadIdx.x, wid = tid >> 5, lane = tid & 31;
    {
        int r = mbase + tid;
        if (e == EE)     { s_tok[tid] = r; s_wt[tid] = 1.f; }
        else if (r < ne) { s_tok[tid] = g_tok[e * CAP + r]; s_wt[tid] = g_wt[e * CAP + r]; }
        else             { s_tok[tid] = 0; s_wt[tid] = 0.f; }
    }
    __syncthreads();

    size_t slotBase = (size_t)e * CAP + mbase;
    size_t koff = (size_t)kh * (HH / 2);

    PROD_SETUP();
    const __half* gsrcA = g_hh + (slotBase + (size_t)tid) * HH + koff;
    const __half* gsrcB = g_wd + (size_t)(e * DD + ntile * 128 + tid) * HH + koff;

    FRAG_SETUP();
    MAINLOOP((HH / 2) / BK);  // 16 chunks per split half

    // epilogue: weighted atomic scatter
    int nv = ne - mbase; if (nv > BM) nv = BM;
    int rq = lane >> 2, cq = lane & 3;
    #pragma unroll
    for (int mb = 0; mb < 4; ++mb)
        #pragma unroll
        for (int nt = 0; nt < 8; ++nt) {
            int nb = nt >> 1, h = nt & 1;
            int col = ntile * BN + wn * 64 + nb * 16 + h * 8 + cq * 2;
            float* c = acc[mb][nt];
            #pragma unroll
            for (int half = 0; half < 2; ++half) {
                int r = wm * 64 + mb * 16 + rq + half * 8;
                if (r < nv) {
                    int tok = s_tok[r]; float wt = s_wt[r];
                    float* orow = out + (size_t)tok * DD + col;
                    atomicAdd(orow,     wt * c[half * 2]);
                    atomicAdd(orow + 1, wt * c[half * 2 + 1]);
                }
            }
        }
}

// ---------------- launch ----------------
extern "C" void kernel_launch(void* const* d_in, const int* in_sizes, int n_in,
                              void* d_out, int out_size) {
    const float* x  = (const float*)d_in[0];
    const float* wr = (const float*)d_in[1];
    const float* Wg = (const float*)d_in[2];
    const float* Wu = (const float*)d_in[3];
    const float* Wd = (const float*)d_in[4];
    const float* sg = (const float*)d_in[5];
    const float* su = (const float*)d_in[6];
    const float* sd = (const float*)d_in[7];
    float* out = (float*)d_out;

    cudaFuncSetAttribute(gemm1_kernel, cudaFuncAttributeMaxDynamicSharedMemorySize, SMEM_DYN);
    cudaFuncSetAttribute(gemm2_kernel, cudaFuncAttributeMaxDynamicSharedMemorySize, SMEM_DYN);

    int n4 = out_size / 4;
    zero_kernel<<<(n4 + 255) / 256, 256>>>((float4*)out, n4);
    conv_x_kernel<<<T_TOK, 256>>>(x);
    conv_wgu_kernel<<<NEXP * 4096, 256>>>(Wg, Wu, sg, su);
    conv_wd_kernel<<<NEXP * DD, 512>>>(Wd, sd);
    router_kernel<<<T_TOK, 256>>>(x, wr);

    dim3 g1(32, 32, NEXP);       // N-tiles(4096/128), M-tiles(4096/128), experts
    gemm1_kernel<<<g1, 128, SMEM_DYN>>>();

    dim3 g2(8, 32, NEXP * 2);    // N-tiles(1024/128), M-tiles, experts x split-K
    gemm2_kernel<<<g2, 128, SMEM_DYN>>>(out);
}

// round 7
// speedup vs baseline: 1.5600x; 1.5600x over previous
#include <cuda_runtime.h>
#include <cuda_fp16.h>
#include <cstdint>
#include <math.h>

// ---------------- problem constants ----------------
#define T_TOK 4096
#define DD    1024
#define HH    2048
#define EE    8
#define CAP   4096
#define NEXP  9          // 8 routed + shared as "expert 8"

// ---------------- tile config ----------------
#define BM 128
#define BN 128
#define BK 64            // k halfs per chunk (128B rows -> SW128)
#define NSTAGE 3
#define S_B   16384      // B plane offset inside a stage
#define STG   32768      // stage bytes: A 16KB + B 16KB
#define SMEM_DYN (NSTAGE * STG)   // 98304

typedef unsigned int u32;
typedef unsigned long long u64;

// ---------------- device scratch ----------------
__device__ int   g_cnt[EE];
__device__ int   g_tok[EE * CAP];
__device__ float g_wt [EE * CAP];
__device__ __half g_xh [(size_t)T_TOK * DD];
__device__ __half g_wgu[(size_t)NEXP * 4096 * DD];   // interleaved gate/up rows
__device__ __half g_wd [(size_t)NEXP * DD * HH];
__device__ __half g_hh [(size_t)NEXP * CAP * HH];

// ---------------- helpers ----------------
__device__ __forceinline__ u32 smem_u32(const void* p) {
    u32 a; asm("{ .reg .u64 t; cvta.to.shared.u64 t, %1; cvt.u32.u64 %0, t; }" : "=r"(a) : "l"(p));
    return a;
}
__device__ __forceinline__ void cpa16(u32 dst, const void* gsrc) {
    asm volatile("cp.async.cg.shared.global [%0], [%1], 16;" :: "r"(dst), "l"(gsrc) : "memory");
}
#define CP_COMMIT() asm volatile("cp.async.commit_group;" ::: "memory")
#define CP_WAIT(n)  asm volatile("cp.async.wait_group %0;" :: "n"(n) : "memory")

__device__ __forceinline__ void ldsm4(u32* r, u32 addr) {
    asm volatile("ldmatrix.sync.aligned.m8n8.x4.shared.b16 {%0,%1,%2,%3}, [%4];"
        : "=r"(r[0]), "=r"(r[1]), "=r"(r[2]), "=r"(r[3]) : "r"(addr));
}
__device__ __forceinline__ void mma16816(float* c, const u32* a, u32 b0, u32 b1) {
    asm volatile("mma.sync.aligned.m16n8k16.row.col.f32.f16.f16.f32 "
        "{%0,%1,%2,%3}, {%4,%5,%6,%7}, {%8,%9}, {%0,%1,%2,%3};"
        : "+f"(c[0]), "+f"(c[1]), "+f"(c[2]), "+f"(c[3])
        : "r"(a[0]), "r"(a[1]), "r"(a[2]), "r"(a[3]), "r"(b0), "r"(b1));
}
__device__ __forceinline__ uint2 pack_hi(float4 v) {
    __half2 h0 = __floats2half2_rn(v.x, v.y);
    __half2 h1 = __floats2half2_rn(v.z, v.w);
    uint2 r; r.x = *(u32*)&h0; r.y = *(u32*)&h1; return r;
}

// ---------------- kernel: zero output ----------------
__global__ void zero_kernel(float4* out4, int n4) {
    int i = blockIdx.x * blockDim.x + threadIdx.x;
    if (i < n4) out4[i] = make_float4(0.f, 0.f, 0.f, 0.f);
}

// ---------------- conversion kernels ----------------
__global__ void conv_x_kernel(const float* __restrict__ x) {
    int t = blockIdx.x, c = threadIdx.x;               // 256 thr = DD/4
    if (blockIdx.x == 0 && threadIdx.x < EE) g_cnt[threadIdx.x] = 0;
    float4 v = ((const float4*)(x + (size_t)t * DD))[c];
    ((uint2*)g_xh)[(size_t)t * 256 + c] = pack_hi(v);
}
__global__ void conv_wgu_kernel(const float* __restrict__ Wg, const float* __restrict__ Wu,
                                const float* __restrict__ sg, const float* __restrict__ su) {
    int b = blockIdx.x;                                 // row in [0, NEXP*4096)
    int e = b >> 12, r = b & 4095;
    const float* src;
    if (e < EE) src = ((r & 1) ? Wu : Wg) + ((size_t)e * HH + (size_t)(r >> 1)) * DD;
    else        src = ((r & 1) ? su : sg) + (size_t)(r >> 1) * DD;
    float4 v = ((const float4*)src)[threadIdx.x];
    ((uint2*)g_wgu)[(size_t)b * 256 + threadIdx.x] = pack_hi(v);
}
__global__ void conv_wd_kernel(const float* __restrict__ Wd, const float* __restrict__ sd) {
    int b = blockIdx.x;                                 // row in [0, NEXP*DD), 512 thr
    int e = b >> 10, d = b & 1023;
    const float* src = (e < EE) ? Wd + ((size_t)e * DD + (size_t)d) * HH
                                : sd + (size_t)d * HH;
    float4 v = ((const float4*)src)[threadIdx.x];
    ((uint2*)g_wd)[(size_t)b * 512 + threadIdx.x] = pack_hi(v);
}

// ---------------- router ----------------
__global__ void router_kernel(const float* __restrict__ x,
                              const float* __restrict__ wr) {
    int t = blockIdx.x, w = threadIdx.x >> 5, lane = threadIdx.x & 31;
    const float* xr = x + (size_t)t * DD;
    const float* wrow = wr + (size_t)w * DD;
    float s = 0.f;
    for (int d = lane; d < DD; d += 32) s += xr[d] * wrow[d];
    #pragma unroll
    for (int o = 16; o; o >>= 1) s += __shfl_xor_sync(0xffffffffu, s, o);
    __shared__ float lg[EE];
    if (lane == 0) lg[w] = s;
    __syncthreads();
    if (threadIdx.x == 0) {
        int i0 = 0; float m0 = lg[0];
        #pragma unroll
        for (int j = 1; j < EE; ++j) if (lg[j] > m0) { m0 = lg[j]; i0 = j; }
        int i1 = -1; float m1 = -INFINITY;
        #pragma unroll
        for (int j = 0; j < EE; ++j) if (j != i0 && lg[j] > m1) { m1 = lg[j]; i1 = j; }
        float w0 = 1.f / (1.f + expf(m1 - m0));
        float w1 = 1.f - w0;
        int p0 = atomicAdd(&g_cnt[i0], 1);
        g_tok[i0 * CAP + p0] = t; g_wt[i0 * CAP + p0] = w0;
        int p1 = atomicAdd(&g_cnt[i1], 1);
        g_tok[i1 * CAP + p1] = t; g_wt[i1 * CAP + p1] = w1;
    }
}

// ---------------- shared GEMM machinery (256 threads, 8 warps, 32x64 warp tile) ----------------
// producer: thread t -> one row (A if t<128 else B), 8x 16B cp.async per chunk.
// SW128 swizzle on 128B rows: dst = (row*128 + q*16) ^ ((row&7)<<4)
#define PROD_SETUP() \
    int prow = tid & 127; \
    u32 pd[8]; \
    { \
        u32 plane = (tid >= 128) ? S_B : 0; \
        u32 psw = (u32)((prow & 7) << 4); \
        _Pragma("unroll") \
        for (int q = 0; q < 8; ++q) \
            pd[q] = plane + (((u32)(prow << 7) + (u32)(q << 4)) ^ psw); \
    }

#define ISSUE(s) do { \
    u32 _st = sb + (u32)((s) % NSTAGE) * STG; \
    const __half* _src = gsrc + (size_t)(s) * BK; \
    _Pragma("unroll") \
    for (int q = 0; q < 8; ++q) cpa16(_st + pd[q], _src + q * 8); \
} while (0)

#define FRAG_SETUP() \
    int wm = wid & 3, wn = wid >> 2; \
    int ks0 = (wid >> 2) << 1;   /* warps sharing an SMSP start at opposite ks phase */ \
    int lr = lane & 15, lkb = lane >> 4; \
    u32 fsw = (u32)((lr & 7) << 4); \
    u32 baseA[2], baseB[4]; \
    _Pragma("unroll") \
    for (int tm = 0; tm < 2; ++tm) \
        baseA[tm] = (u32)((wm * 32 + tm * 16 + lr) * 128 + lkb * 16); \
    _Pragma("unroll") \
    for (int nb = 0; nb < 4; ++nb) \
        baseB[nb] = (u32)(S_B + (wn * 64 + nb * 16 + lr) * 128 + lkb * 16); \
    float acc[2][8][4]; \
    _Pragma("unroll") \
    for (int a_ = 0; a_ < 2; ++a_) \
        _Pragma("unroll") \
        for (int b_ = 0; b_ < 8; ++b_) \
            _Pragma("unroll") \
            for (int c_ = 0; c_ < 4; ++c_) acc[a_][b_][c_] = 0.f;

// ks order staggered per warp: (ks0+i)&3 — keeps LDS crossbar and tensor pipe
// simultaneously busy across the warps of an SMSP instead of alternating in phase.
#define CONSUME(cur) \
    _Pragma("unroll") \
    for (int i_ = 0; i_ < 4; ++i_) { \
        int ks = (ks0 + i_) & 3; \
        u32 af[2][4], bf[4][4]; \
        _Pragma("unroll") \
        for (int tm = 0; tm < 2; ++tm) \
            ldsm4(af[tm], (cur) + ((baseA[tm] + ks * 32) ^ fsw)); \
        _Pragma("unroll") \
        for (int nb = 0; nb < 4; ++nb) \
            ldsm4(bf[nb], (cur) + ((baseB[nb] + ks * 32) ^ fsw)); \
        _Pragma("unroll") \
        for (int mt = 0; mt < 2; ++mt) \
            _Pragma("unroll") \
            for (int nb = 0; nb < 4; ++nb) { \
                mma16816(acc[mt][nb * 2],     af[mt], bf[nb][0], bf[nb][2]); \
                mma16816(acc[mt][nb * 2 + 1], af[mt], bf[nb][1], bf[nb][3]); \
            } \
    }

#define MAINLOOP(NC) \
    ISSUE(0); CP_COMMIT(); \
    ISSUE(1); CP_COMMIT(); \
    for (int kt = 0; kt < (NC); ++kt) { \
        CP_WAIT(1); \
        __syncthreads(); \
        if (kt + 2 < (NC)) ISSUE(kt + 2); \
        CP_COMMIT(); \
        u32 cur = sb + (u32)(kt % NSTAGE) * STG; \
        CONSUME(cur); \
    }

// =====================================================================
// GEMM1: C[128,128] = Xg[128,1024] . Wgu^T ; epilogue SwiGLU -> g_hh
// =====================================================================
__global__ void __launch_bounds__(256, 2)
gemm1_kernel() {
    int e = blockIdx.z;
    int ne = (e == EE) ? T_TOK : g_cnt[e];
    int mbase = blockIdx.y * BM;
    if (mbase >= ne) return;
    int ntile = blockIdx.x;

    extern __shared__ char smem[];
    u32 sb = smem_u32(smem);
    __shared__ int s_tok[128];
    int tid = threadIdx.x, wid = tid >> 5, lane = tid & 31;
    if (tid < 128) {
        int r = mbase + tid;
        s_tok[tid] = (e == EE) ? r : ((r < ne) ? g_tok[e * CAP + r] : g_tok[e * CAP]);
    }
    __syncthreads();

    PROD_SETUP();
    const __half* gsrc;
    if (tid < 128) gsrc = g_xh + (size_t)s_tok[prow] * DD;
    else           gsrc = g_wgu + (size_t)(e * 4096 + ntile * 128 + prow) * DD;

    FRAG_SETUP();
    MAINLOOP(DD / BK);   // 16 chunks

    // epilogue: SwiGLU -> fp16 h
    size_t slotBase = (size_t)e * CAP + mbase;
    int rbase = wm * 32 + (lane >> 2), cquad = lane & 3;
    #pragma unroll
    for (int mt = 0; mt < 2; ++mt)
        #pragma unroll
        for (int nt = 0; nt < 8; ++nt) {
            int hcol = ntile * 64 + wn * 32 + nt * 4 + cquad;
            float* c = acc[mt][nt];
            #pragma unroll
            for (int half = 0; half < 2; ++half) {
                int r = rbase + mt * 16 + half * 8;
                float gv = c[half * 2], uv = c[half * 2 + 1];
                float h = (gv / (1.f + __expf(-gv))) * uv;
                g_hh[(slotBase + (size_t)r) * HH + (size_t)hcol] = __float2half_rn(h);
            }
        }
}

// =====================================================================
// GEMM2: C[128,128] = h[128,2048] . Wd^T ; split-K=2; atomic scatter
// =====================================================================
__global__ void __launch_bounds__(256, 2)
gemm2_kernel(float* __restrict__ out) {
    int z = blockIdx.z;
    int e = z >> 1, kh = z & 1;
    int ne = (e == EE) ? T_TOK : g_cnt[e];
    int mbase = blockIdx.y * BM;
    if (mbase >= ne) return;
    int ntile = blockIdx.x;

    extern __shared__ char smem[];
    u32 sb = smem_u32(smem);
    __shared__ int   s_tok[128];
    __shared__ float s_wt[128];
    int tid = threadIdx.x, wid = tid >> 5, lane = tid & 31;
    if (tid < 128) {
        int r = mbase + tid;
        if (e == EE)     { s_tok[tid] = r; s_wt[tid] = 1.f; }
        else if (r < ne) { s_tok[tid] = g_tok[e * CAP + r]; s_wt[tid] = g_wt[e * CAP + r]; }
        else             { s_tok[tid] = 0; s_wt[tid] = 0.f; }
    }
    __syncthreads();

    size_t slotBase = (size_t)e * CAP + mbase;
    size_t koff = (size_t)kh * (HH / 2);

    PROD_SETUP();
    const __half* gsrc;
    if (tid < 128) gsrc = g_hh + (slotBase + (size_t)prow) * HH + koff;
    else           gsrc = g_wd + (size_t)(e * DD + ntile * 128 + prow) * HH + koff;

    FRAG_SETUP();
    MAINLOOP((HH / 2) / BK);  // 16 chunks per split half

    // epilogue: weighted atomic scatter
    int nv = ne - mbase; if (nv > BM) nv = BM;
    int rbase = wm * 32 + (lane >> 2), cquad = lane & 3;
    #pragma unroll
    for (int mt = 0; mt < 2; ++mt)
        #pragma unroll
        for (int nt = 0; nt < 8; ++nt) {
            int col = ntile * BN + wn * 64 + nt * 8 + cquad * 2;
            float* c = acc[mt][nt];
            #pragma unroll
            for (int half = 0; half < 2; ++half) {
                int r = rbase + mt * 16 + half * 8;
                if (r < nv) {
                    int tok = s_tok[r]; float wt = s_wt[r];
                    float* orow = out + (size_t)tok * DD + col;
                    atomicAdd(orow,     wt * c[half * 2]);
                    atomicAdd(orow + 1, wt * c[half * 2 + 1]);
                }
            }
        }
}

// ---------------- launch ----------------
extern "C" void kernel_launch(void* const* d_in, const int* in_sizes, int n_in,
                              void* d_out, int out_size) {
    const float* x  = (const float*)d_in[0];
    const float* wr = (const float*)d_in[1];
    const float* Wg = (const float*)d_in[2];
    const float* Wu = (const float*)d_in[3];
    const float* Wd = (const float*)d_in[4];
    const float* sg = (const float*)d_in[5];
    const float* su = (const float*)d_in[6];
    const float* sd = (const float*)d_in[7];
    float* out = (float*)d_out;

    cudaFuncSetAttribute(gemm1_kernel, cudaFuncAttributeMaxDynamicSharedMemorySize, SMEM_DYN);
    cudaFuncSetAttribute(gemm2_kernel, cudaFuncAttributeMaxDynamicSharedMemorySize, SMEM_DYN);

    // order chosen so gemm1 is launch #4 (the slot ncu has been profiling)
    conv_x_kernel<<<T_TOK, 256>>>(x);                 // also inits g_cnt
    router_kernel<<<T_TOK, 256>>>(x, wr);
    conv_wgu_kernel<<<NEXP * 4096, 256>>>(Wg, Wu, sg, su);

    dim3 g1(32, 32, NEXP);       // N-tiles(4096/128), M-tiles(4096/128), experts
    gemm1_kernel<<<g1, 256, SMEM_DYN>>>();

    int n4 = out_size / 4;
    zero_kernel<<<(n4 + 255) / 256, 256>>>((float4*)out, n4);
    conv_wd_kernel<<<NEXP * DD, 512>>>(Wd, sd);

    dim3 g2(8, 32, NEXP * 2);    // N-tiles(1024/128), M-tiles, experts x split-K
    gemm2_kernel<<<g2, 256, SMEM_DYN>>>(out);
}